// round 16
// baseline (speedup 1.0000x reference)
#include <cuda_runtime.h>
#include <cuda_fp16.h>
#include <math.h>
#include <stdint.h>

#define B_   64
#define L_   1024
#define ENC_ 2048
#define DEC_ 512
#define ATT_ 512
#define BL_  (B_ * L_)

// ---------------------------------------------------------------------------
// Device scratch
// ---------------------------------------------------------------------------
__device__ float g_H[B_ * ATT_];                          // proj_h + b2 + b1
// W1 fp16, layout [c=k/64][n 512][k 64]
__device__ __align__(128) __half g_B16[ENC_ * ATT_];
// F fp16, layout [mb][c][row 128][k 64] — written by score (ncp==0 CTAs)
__device__ __align__(128) __half g_F16[(size_t)BL_ * ENC_];
__device__ float g_scorep[2 * BL_];                       // per-N-half score partials
__device__ float g_ctxp[8 * B_ * ENC_];                   // context partials

// ---------------------------------------------------------------------------
// Helpers
// ---------------------------------------------------------------------------
__device__ __forceinline__ uint32_t smem_u32(const void* p) {
    uint32_t a;
    asm("{ .reg .u64 t; cvta.to.shared.u64 t, %1; cvt.u32.u64 %0, t; }" : "=r"(a) : "l"(p));
    return a;
}
__device__ __forceinline__ void cp16(uint32_t dst, const void* src) {
    asm volatile("cp.async.cg.shared.global [%0], [%1], 16;" :: "r"(dst), "l"(src));
}
__device__ __forceinline__ void cp_commit() {
    asm volatile("cp.async.commit_group;" ::: "memory");
}
__device__ __forceinline__ void cp_wait0() {
    asm volatile("cp.async.wait_group 0;" ::: "memory");
}
__device__ __forceinline__ void cp_wait1() {
    asm volatile("cp.async.wait_group 1;" ::: "memory");
}
__device__ __forceinline__ void ldsm_x4(uint32_t* r, uint32_t addr) {
    asm volatile("ldmatrix.sync.aligned.m8n8.x4.shared.b16 {%0,%1,%2,%3}, [%4];"
                 : "=r"(r[0]), "=r"(r[1]), "=r"(r[2]), "=r"(r[3]) : "r"(addr));
}
__device__ __forceinline__ void mma_f16(float* d, const uint32_t* a, const uint32_t* b) {
    asm volatile(
        "mma.sync.aligned.m16n8k16.row.col.f32.f16.f16.f32 "
        "{%0,%1,%2,%3}, {%4,%5,%6,%7}, {%8,%9}, {%0,%1,%2,%3};"
        : "+f"(d[0]), "+f"(d[1]), "+f"(d[2]), "+f"(d[3])
        : "r"(a[0]), "r"(a[1]), "r"(a[2]), "r"(a[3]), "r"(b[0]), "r"(b[1]));
}
__device__ __forceinline__ float fast_tanh(float x) {
    float e = __expf(2.f * x);
    return __fdividef(e - 1.f, e + 1.f);
}

// ---------------------------------------------------------------------------
// Kernel A: H = hidden @ W2 + b2 + b1
// ---------------------------------------------------------------------------
__global__ void proj_h_kernel(const float* __restrict__ hidden,
                              const float* __restrict__ W2,
                              const float* __restrict__ b2,
                              const float* __restrict__ b1) {
    __shared__ float hs[DEC_];
    int b = blockIdx.x, a = threadIdx.x;
    hs[a] = hidden[b * DEC_ + a];
    __syncthreads();
    float acc = 0.f;
#pragma unroll 8
    for (int d = 0; d < DEC_; ++d) acc += hs[d] * W2[d * ATT_ + a];
    g_H[b * ATT_ + a] = acc + b2[a] + b1[a];
}

// ---------------------------------------------------------------------------
// Kernel B: W1 [ENC, ATT] fp32 -> fp16, layout [c=k/64][n][k64]
// ---------------------------------------------------------------------------
__global__ void prep_B_kernel(const float* __restrict__ W1) {
    int idx = blockIdx.x * 256 + threadIdx.x;   // idx = k*512 + n
    if (idx >= ENC_ * ATT_) return;
    int k = idx >> 9, n = idx & 511;
    int c = k >> 6, kk = k & 63;
    g_B16[((size_t)(c * 512 + n) << 6) + kk] = __float2half_rn(W1[idx]);
}

// ---------------------------------------------------------------------------
// Kernel C: fused fp16 GEMM + in-kernel A conversion + tanh + V-reduction
// Grid: (2 ncp, 512 mb), ncp fastest (pair shares F via L2).
// CTA: 128x256 tile, 512 thr (4wm x 4wn), KC=64, 3 stages (wait_group 1).
// A: fp32 LDG->cvt->STS; ncp==0 CTA also STGs fp16 tiles to g_F16.
// B: fp16 cp.async + paired ldsm.
// ---------------------------------------------------------------------------
static constexpr int PITCH   = 144;              // 128B data + 16B pad
static constexpr int A_TILE  = 128 * PITCH;      // 18432
static constexpr int B_TILE  = 256 * PITCH;      // 36864
static constexpr int STAGE   = A_TILE + B_TILE;  // 55296
static constexpr int NSTG    = 3;
static constexpr int OFF_A   = 0;
static constexpr int OFF_B   = A_TILE;
static constexpr int OFF_PART = NSTG * STAGE;         // 165888: 4*128 floats
static constexpr int OFF_H    = OFF_PART + 2048;
static constexpr int OFF_V    = OFF_H + 1024;
static constexpr int SMEM_TOTAL = OFF_V + 1024;       // 169984
static constexpr int NCHUNK  = ENC_ / 64;             // 32

__global__ __launch_bounds__(512, 1) void score_mma_kernel(
    const float* __restrict__ F, const float* __restrict__ V)
{
    extern __shared__ char smem[];
    const uint32_t sb = smem_u32(smem);
    const int tid  = threadIdx.x;
    const int lane = tid & 31;
    const int wid  = tid >> 5;
    const int wm   = wid & 3;        // warp m: 4 x 32 rows
    const int wn   = wid >> 2;       // warp n: 4 x 64 cols
    const int ncp  = blockIdx.x;     // n half (256 cols)
    const int mb   = blockIdx.y;
    const int m0   = mb * 128;
    const int b    = mb >> 3;

    float* partS = (float*)(smem + OFF_PART);
    float* Hs    = (float*)(smem + OFF_H);
    float* Vs    = (float*)(smem + OFF_V);
    if (tid < 256) {
        Hs[tid] = g_H[b * ATT_ + ncp * 256 + tid];
        Vs[tid] = V[ncp * 256 + tid];
    }

    float d[2][8][4];
#pragma unroll
    for (int mt = 0; mt < 2; ++mt)
#pragma unroll
        for (int nt = 0; nt < 8; ++nt)
#pragma unroll
            for (int e = 0; e < 4; ++e) d[mt][nt][e] = 0.f;

    // A: 128x64 fp32 per chunk = 2048 float4 / 512 thr = 4/thread
    const char* pFb = (const char*)(F + (size_t)m0 * ENC_);   // +256B per chunk
    char*       pOb = (char*)(g_F16 + ((size_t)mb * 32 * 128 << 6)); // +16384B per chunk
    uint32_t aSrc[4], aDst[4], oOff[4];
#pragma unroll
    for (int t = 0; t < 4; ++t) {
        int v = tid + t * 512, row = v >> 4, q = v & 15;
        aSrc[t] = (uint32_t)(row * (ENC_ * 4) + q * 16);
        aDst[t] = (uint32_t)(OFF_A + row * PITCH + q * 8);
        oOff[t] = (uint32_t)((row * 64 + q * 4) * 2);
    }
    // B: 256 rows x 128B per chunk = 2048 x16B / 512 thr = 4/thread
    const char* pBb = (const char*)(g_B16 + ((size_t)(ncp * 256) << 6)); // +65536B per chunk
    uint32_t bSrc[4], bDst[4];
#pragma unroll
    for (int e = 0; e < 4; ++e) {
        int j = tid + e * 512, row = j >> 3, q = j & 7;
        bSrc[e] = (uint32_t)((row * 64 + q * 8) * 2);
        bDst[e] = (uint32_t)(OFF_B + row * PITCH + q * 16);
    }

    // ---- prologue ----
    float4 fr[4];
    // chunk 0: A direct, B group 0 -> stage 0
#pragma unroll
    for (int t = 0; t < 4; ++t) fr[t] = *(const float4*)(pFb + aSrc[t]);
#pragma unroll
    for (int e = 0; e < 4; ++e) cp16(sb + bDst[e], pBb + bSrc[e]);
    cp_commit();
#pragma unroll
    for (int t = 0; t < 4; ++t) {
        __half2 h01 = __floats2half2_rn(fr[t].x, fr[t].y);
        __half2 h23 = __floats2half2_rn(fr[t].z, fr[t].w);
        uint2 v = make_uint2(*(uint32_t*)&h01, *(uint32_t*)&h23);
        *(uint2*)(smem + aDst[t]) = v;
        if (ncp == 0) *(uint2*)(pOb + oOff[t]) = v;
    }
    pFb += 256;  pBb += 65536;  pOb += 16384;
    // chunk 1: B group 1 -> stage 1; A(1) into regs (STS'd at iter 0)
#pragma unroll
    for (int e = 0; e < 4; ++e) cp16(sb + STAGE + bDst[e], pBb + bSrc[e]);
    cp_commit();
#pragma unroll
    for (int t = 0; t < 4; ++t) fr[t] = *(const float4*)(pFb + aSrc[t]);
    pFb += 256;  pBb += 65536;

    // ldsm base offsets (stage-relative)
    const uint32_t aoff0 = OFF_A + (uint32_t)(wm * 32 + (lane & 15)) * PITCH +
                           (uint32_t)(((lane >> 4) & 1) * 16);
    const uint32_t aoff1 = aoff0 + 16 * PITCH;
    uint32_t boff[4];
#pragma unroll
    for (int p = 0; p < 4; ++p)
        boff[p] = OFF_B + (uint32_t)(wn * 64 + p * 16 + (lane & 15)) * PITCH +
                  (uint32_t)(((lane >> 4) & 1) * 16);

    int sc = 0;   // stage of chunk i
#pragma unroll 1
    for (int i = 0; i < NCHUNK; ++i) {
        const uint32_t stg = sb + sc * STAGE;
        const int nxt = (sc + 1 == NSTG) ? 0 : sc + 1;   // stage of chunk i+1
        const int nn  = (nxt + 1 == NSTG) ? 0 : nxt + 1; // stage of chunk i+2
        sc = nxt;

        if (i >= NCHUNK - 2) cp_wait0(); else cp_wait1();
        __syncthreads();   // compute(i-1) finished; buffers nxt/nn reusable

        if (i + 1 < NCHUNK) {
            // convert + store A(i+1) (regs already loaded)
#pragma unroll
            for (int t = 0; t < 4; ++t) {
                __half2 h01 = __floats2half2_rn(fr[t].x, fr[t].y);
                __half2 h23 = __floats2half2_rn(fr[t].z, fr[t].w);
                uint2 v = make_uint2(*(uint32_t*)&h01, *(uint32_t*)&h23);
                *(uint2*)((char*)smem + nxt * STAGE + aDst[t]) = v;
                if (ncp == 0) *(uint2*)(pOb + oOff[t]) = v;
            }
            pOb += 16384;
        }
        if (i + 2 < NCHUNK) {
            // B(i+2) copies + A(i+2) reg prefetch
#pragma unroll
            for (int e = 0; e < 4; ++e) cp16(sb + nn * STAGE + bDst[e], pBb + bSrc[e]);
            cp_commit();
#pragma unroll
            for (int t = 0; t < 4; ++t) fr[t] = *(const float4*)(pFb + aSrc[t]);
            pFb += 256;  pBb += 65536;
        }

        // ---- compute chunk i on stage stg: 4 k16 slabs ----
#pragma unroll
        for (int kk = 0; kk < 4; ++kk) {
            const uint32_t ko = (uint32_t)(kk * 32);
            uint32_t a0[4], a1[4];
            ldsm_x4(a0, stg + aoff0 + ko);
            ldsm_x4(a1, stg + aoff1 + ko);
            uint32_t bb[8][2];
#pragma unroll
            for (int p = 0; p < 4; ++p) {       // paired ldsm: 2 n-tiles per x4
                uint32_t r[4];
                ldsm_x4(r, stg + boff[p] + ko);
                bb[2 * p][0]     = r[0];
                bb[2 * p + 1][0] = r[1];
                bb[2 * p][1]     = r[2];
                bb[2 * p + 1][1] = r[3];
            }
#pragma unroll
            for (int nt = 0; nt < 8; ++nt) {
                mma_f16(d[0][nt], a0, bb[nt]);
                mma_f16(d[1][nt], a1, bb[nt]);
            }
        }
    }

    // ---- epilogue: tanh + V-weighted row reduction over this 256-col half ----
#pragma unroll
    for (int mt = 0; mt < 2; ++mt) {
        float s0 = 0.f, s1 = 0.f;
#pragma unroll
        for (int nt = 0; nt < 8; ++nt) {
            int c0 = wn * 64 + nt * 8 + (lane & 3) * 2;
            float h0 = Hs[c0], v0 = Vs[c0];
            float h1 = Hs[c0 + 1], v1 = Vs[c0 + 1];
            s0 += fast_tanh(d[mt][nt][0] + h0) * v0 + fast_tanh(d[mt][nt][1] + h1) * v1;
            s1 += fast_tanh(d[mt][nt][2] + h0) * v0 + fast_tanh(d[mt][nt][3] + h1) * v1;
        }
#pragma unroll
        for (int o = 1; o <= 2; o <<= 1) {
            s0 += __shfl_xor_sync(~0u, s0, o);
            s1 += __shfl_xor_sync(~0u, s1, o);
        }
        if ((lane & 3) == 0) {
            int r = wm * 32 + mt * 16 + (lane >> 2);
            partS[wn * 128 + r]     = s0;
            partS[wn * 128 + r + 8] = s1;
        }
    }
    __syncthreads();
    if (tid < 128)
        g_scorep[ncp * BL_ + m0 + tid] = partS[tid] + partS[128 + tid] +
                                         partS[256 + tid] + partS[384 + tid];
}

// ---------------------------------------------------------------------------
// Kernel D: combine partials + softmax over L per batch
// ---------------------------------------------------------------------------
__global__ void softmax_kernel(const float* __restrict__ bv, float* __restrict__ w) {
    __shared__ float redm[32];
    __shared__ float reds[32];
    const int b = blockIdx.x, t = threadIdx.x;
    const int idx = b * L_ + t;
    float s = g_scorep[idx] + g_scorep[BL_ + idx] + bv[0];
    float m = s;
#pragma unroll
    for (int o = 16; o > 0; o >>= 1) m = fmaxf(m, __shfl_xor_sync(~0u, m, o));
    if ((t & 31) == 0) redm[t >> 5] = m;
    __syncthreads();
    if (t < 32) {
        float v = redm[t];
#pragma unroll
        for (int o = 16; o > 0; o >>= 1) v = fmaxf(v, __shfl_xor_sync(~0u, v, o));
        redm[t] = v;
    }
    __syncthreads();
    m = redm[0];
    const float e = expf(s - m);
    float sum = e;
#pragma unroll
    for (int o = 16; o > 0; o >>= 1) sum += __shfl_xor_sync(~0u, sum, o);
    if ((t & 31) == 0) reds[t >> 5] = sum;
    __syncthreads();
    if (t < 32) {
        float v = reds[t];
#pragma unroll
        for (int o = 16; o > 0; o >>= 1) v += __shfl_xor_sync(~0u, v, o);
        reds[t] = v;
    }
    __syncthreads();
    w[idx] = e / reds[0];
}

// ---------------------------------------------------------------------------
// Kernel E/F: context = sum_l w*F  (fp16 tiles from score; 8 L-partials)
// ---------------------------------------------------------------------------
__global__ void context_part_kernel(const float* __restrict__ w) {
    __shared__ float ws[128];
    const int b = blockIdx.y, z = blockIdx.z, t = threadIdx.x;
    ws[t] = w[b * L_ + z * 128 + t];
    __syncthreads();
    const int e0 = blockIdx.x * 512 + t * 4;
    const int mb = b * 8 + z;
    const int c  = e0 >> 6, kk = e0 & 63;
    const __half* base = g_F16 + (((size_t)(mb * 32 + c) * 128) << 6) + kk;
    float4 acc = make_float4(0.f, 0.f, 0.f, 0.f);
#pragma unroll 4
    for (int l = 0; l < 128; ++l) {
        uint2 v = *(const uint2*)(base + ((size_t)l << 6));
        float2 f01 = __half22float2(*(const __half2*)&v.x);
        float2 f23 = __half22float2(*(const __half2*)&v.y);
        const float wl = ws[l];
        acc.x += wl * f01.x; acc.y += wl * f01.y;
        acc.z += wl * f23.x; acc.w += wl * f23.y;
    }
    *(float4*)&g_ctxp[(size_t)(z * B_ + b) * ENC_ + e0] = acc;
}

__global__ void context_reduce_kernel(float* __restrict__ ctx) {
    const int i = (blockIdx.x * 256 + threadIdx.x) * 4;
    float4 acc = make_float4(0.f, 0.f, 0.f, 0.f);
#pragma unroll
    for (int p = 0; p < 8; ++p) {
        float4 a = *(const float4*)&g_ctxp[(size_t)p * B_ * ENC_ + i];
        acc.x += a.x; acc.y += a.y; acc.z += a.z; acc.w += a.w;
    }
    *(float4*)&ctx[i] = acc;
}

// ---------------------------------------------------------------------------
// Launch
// ---------------------------------------------------------------------------
extern "C" void kernel_launch(void* const* d_in, const int* in_sizes, int n_in,
                              void* d_out, int out_size) {
    const float* F   = (const float*)d_in[0];
    const float* hid = (const float*)d_in[1];
    const float* W1  = (const float*)d_in[2];
    const float* b1  = (const float*)d_in[3];
    const float* W2  = (const float*)d_in[4];
    const float* b2  = (const float*)d_in[5];
    const float* V   = (const float*)d_in[6];
    const float* bv  = (const float*)d_in[7];

    float* out = (float*)d_out;
    float* ctx = out;
    float* wts = out + B_ * ENC_;

    cudaFuncSetAttribute(score_mma_kernel,
                         cudaFuncAttributeMaxDynamicSharedMemorySize, SMEM_TOTAL);

    proj_h_kernel<<<B_, ATT_>>>(hid, W2, b2, b1);
    prep_B_kernel<<<(ENC_ * ATT_) / 256, 256>>>(W1);
    score_mma_kernel<<<dim3(2, BL_ / 128), 512, SMEM_TOTAL>>>(F, V);
    softmax_kernel<<<B_, L_>>>(bv, wts);
    context_part_kernel<<<dim3(ENC_ / 512, B_, 8), 128>>>(wts);
    context_reduce_kernel<<<(B_ * ENC_) / 1024, 256>>>(ctx);
}